// round 10
// baseline (speedup 1.0000x reference)
#include <cuda_runtime.h>
#include <math.h>

// LineFinderLoss, S = 4096 (square). Output tuple packed: d_out[0] = loss,
// d_out[1 + i*S + j] = cost[i][j].
//
// cost[i][j] = 0.5*((in[i,0]-tg[j,0])^2 + (in[i,1]-tg[j,1])^2)
// loss = ALPHA*sum((in-tg)^2) - S*sum_n log(in[n,4]) + sum_ij (in[j,3]-tg[i,j])^2 / S^2

#define MAXS    4096
#define ALPHA   0.01
#define RTILE   4          // rows per ticket
#define OCC     5          // 5 blocks/SM -> 51-reg budget, 40 warps/SM
#define GRID    (148 * OCC)   // 740 blocks -> 5920 warps, 185 per slice
#define NSLICE  32            // column slices of 128 cols (32 float4 per warp)
#define TSTRIDE 64            // uints between counters (256B: avoids LTS bit-7 pairing)

// ---------------- device scratch (no allocations allowed) ----------------
// Shifted packed columns: g_t0s[k] = target[k-1, 0]  (k = 1..S), g_t0s[0] junk.
__device__ float  g_t0s[MAXS + 4];
__device__ float  g_t1s[MAXS + 4];
__device__ float  g_ic3[MAXS + 4];       // input[:,3] (unshifted)
__device__ float  g_a0[MAXS];            // input[:,0]  (row scalars)
__device__ float  g_a1[MAXS];            // input[:,1]
__device__ double g_sumlog;              // sum_n log(input[n,4])
__device__ double g_sum_sq;
__device__ double g_sum_t3;
__device__ unsigned int g_tick[NSLICE * TSTRIDE];  // per-slice row-group counters
__device__ unsigned int g_count;         // completion counter

// ---------------- kernel 1: reset state + warp-per-row gather ---------------
// One warp per row: the 5 scattered scalar loads issue in parallel across
// lanes (one latency round trip instead of five). All replay-state resets
// live here, ordered before main_kernel by the kernel boundary.
__global__ void pack_kernel(const float* __restrict__ inp,
                            const float* __restrict__ tgt, int S) {
    if (blockIdx.x == 0) {
        if (threadIdx.x < NSLICE) g_tick[threadIdx.x * TSTRIDE] = 0u;
        if (threadIdx.x == 0) {
            g_count  = 0u;
            g_sum_sq = 0.0;
            g_sum_t3 = 0.0;
            g_sumlog = 0.0;
        }
    }
    const int lane = threadIdx.x & 31;
    const int r    = (blockIdx.x * blockDim.x + threadIdx.x) >> 5;  // row = global warp
    float lg = 0.0f;
    if (r < S) {
        const size_t base = (size_t)r * S;
        switch (lane) {
            case 0: g_t0s[r + 1] = tgt[base + 0]; break;
            case 1: g_t1s[r + 1] = tgt[base + 1]; break;
            case 2: g_a0[r]      = inp[base + 0]; break;
            case 3: g_a1[r]      = inp[base + 1]; break;
            case 4: g_ic3[r]     = inp[base + 3]; break;
            case 5: lg = logf(inp[base + 4]); break;
            case 6: if (r == 0) { g_t0s[0] = 0.0f; g_t1s[0] = 0.0f; } break;
            default: break;
        }
    }
    // gather lane-5's lg per warp, block-sum, one double atomic per block
    lg = __shfl_sync(0xffffffffu, lg, 5);
    __shared__ float slg[8];
    if (lane == 0) slg[threadIdx.x >> 5] = lg;
    __syncthreads();
    if (threadIdx.x == 0) {
        float s = 0.0f;
        #pragma unroll
        for (int w = 0; w < 8; w++) s += slg[w];
        atomicAdd(&g_sumlog, (double)s);
    }
}

// ---------------- per-row worker for main kernel ---------------------------
__device__ __forceinline__ void do_row(
    const float4 in, const float4 tg, int row, size_t base, int j4,
    bool isFirst, bool isLast,
    const float4 t0s, const float4 t1s, const float4 c3,
    float* __restrict__ out, int S,
    float& accq, float& acct)
{
    const float a0 = g_a0[row];   // broadcast, L1-resident
    const float a1 = g_a1[row];

    float d, e, u, v;
    d = in.x - tg.x; accq = fmaf(d, d, accq);
    e = c3.x - tg.x; acct = fmaf(e, e, acct);
    d = in.y - tg.y; accq = fmaf(d, d, accq);
    e = c3.y - tg.y; acct = fmaf(e, e, acct);
    d = in.z - tg.z; accq = fmaf(d, d, accq);
    e = c3.z - tg.z; acct = fmaf(e, e, acct);
    d = in.w - tg.w; accq = fmaf(d, d, accq);
    e = c3.w - tg.w; acct = fmaf(e, e, acct);

    float4 cv;
    u = a0 - t0s.x; v = a1 - t1s.x; cv.x = 0.5f * fmaf(u, u, v * v);
    u = a0 - t0s.y; v = a1 - t1s.y; cv.y = 0.5f * fmaf(u, u, v * v);
    u = a0 - t0s.z; v = a1 - t1s.z; cv.z = 0.5f * fmaf(u, u, v * v);
    u = a0 - t0s.w; v = a1 - t1s.w; cv.w = 0.5f * fmaf(u, u, v * v);

    if (!isFirst) {
        // out + base + 4*j4 == cost + base + (4*j4 - 1), 16B aligned
        ((float4*)(out + base))[j4] = cv;
    } else {
        float* crow = out + 1 + base;   // cost row start (cols 0..2)
        crow[0] = cv.y; crow[1] = cv.z; crow[2] = cv.w;
    }
    if (isLast) {
        u = a0 - g_t0s[S]; v = a1 - g_t1s[S];
        out[1 + base + (size_t)(S - 1)] = 0.5f * fmaf(u, u, v * v);
    }
}

// ---------------- kernel 2: per-warp slices + per-warp tickets --------------
// Each WARP owns a fixed 128-column slice (t0s/t1s/c3 in registers, loaded
// once) and pops 4-row groups from its slice's counter. NO barriers in the
// loop: warps free-run. The group body is SOFTWARE-PIPELINED in two halves
// (load A,B -> compute A,B -> load C,D -> compute C,D) so peak live float4
// count fits a 51-reg budget, allowing 5 blocks/SM (40 warps) instead of 4.
// The next ticket is popped at body start (lane 0) and consumed by __shfl
// only at body end, hiding the ATOMG latency under the body.
// Hard-bounded loop: terminates even on corrupt counter state.
__global__ __launch_bounds__(256, OCC)
void main_kernel(const float* __restrict__ inp,
                 const float* __restrict__ tgt,
                 float* __restrict__ out, int S) {
    const int lane  = threadIdx.x & 31;
    const int wid   = threadIdx.x >> 5;
    const int gw    = blockIdx.x * 8 + wid;          // global warp id
    const int slice = gw & (NSLICE - 1);
    const int j4    = slice * 32 + lane;             // float4 column index
    const int lastj4 = (S >> 2) - 1;
    const int groups = S / RTILE;                    // 1024
    const bool isFirst = (j4 == 0);
    const bool isLast  = (j4 == lastj4);

    // column-resident data: loaded ONCE per warp, lives in registers
    const float4 t0s = ((const float4*)g_t0s)[j4];   // t0[4j-1..4j+2]
    const float4 t1s = ((const float4*)g_t1s)[j4];
    const float4 c3  = ((const float4*)g_ic3)[j4];   // in[4j..4j+3, 3]

    unsigned int* tick = &g_tick[slice * TSTRIDE];
    float acc_sq0 = 0.0f, acc_sq1 = 0.0f;
    float acc_t30 = 0.0f, acc_t31 = 0.0f;

    unsigned int t = 0;
    if (lane == 0) t = atomicAdd(tick, 1u);
    t = __shfl_sync(0xffffffffu, t, 0);

    for (int p = 0; p < groups + 2; p++) {
        if (t >= (unsigned int)groups) break;
        unsigned int tn = 0;
        if (lane == 0) tn = atomicAdd(tick, 1u);     // prefetch (consumed at end)

        const int r0 = (int)t * RTILE;
        const size_t b0 = (size_t)r0 * S;

        // ---- half 1: rows A,B ----
        {
            const float4 iA = __ldcs((const float4*)(inp + b0) + j4);
            const float4 gA = __ldcs((const float4*)(tgt + b0) + j4);
            const float4 iB = __ldcs((const float4*)(inp + b0 + S) + j4);
            const float4 gB = __ldcs((const float4*)(tgt + b0 + S) + j4);
            do_row(iA, gA, r0 + 0, b0,     j4, isFirst, isLast,
                   t0s, t1s, c3, out, S, acc_sq0, acc_t30);
            do_row(iB, gB, r0 + 1, b0 + S, j4, isFirst, isLast,
                   t0s, t1s, c3, out, S, acc_sq1, acc_t31);
        }
        // ---- half 2: rows C,D ----
        {
            const float4 iC = __ldcs((const float4*)(inp + b0 + 2 * (size_t)S) + j4);
            const float4 gC = __ldcs((const float4*)(tgt + b0 + 2 * (size_t)S) + j4);
            const float4 iD = __ldcs((const float4*)(inp + b0 + 3 * (size_t)S) + j4);
            const float4 gD = __ldcs((const float4*)(tgt + b0 + 3 * (size_t)S) + j4);
            do_row(iC, gC, r0 + 2, b0 + 2 * (size_t)S, j4, isFirst, isLast,
                   t0s, t1s, c3, out, S, acc_sq0, acc_t30);
            do_row(iD, gD, r0 + 3, b0 + 3 * (size_t)S, j4, isFirst, isLast,
                   t0s, t1s, c3, out, S, acc_sq1, acc_t31);
        }

        t = __shfl_sync(0xffffffffu, tn, 0);         // consume prefetched ticket
    }

    float acc_sq = acc_sq0 + acc_sq1;
    float acc_t3 = acc_t30 + acc_t31;

    // block reduce (warps re-converge here after independent loops)
    #pragma unroll
    for (int off = 16; off > 0; off >>= 1) {
        acc_sq += __shfl_down_sync(0xffffffffu, acc_sq, off);
        acc_t3 += __shfl_down_sync(0xffffffffu, acc_t3, off);
    }
    __shared__ float s_sq[8], s_t3[8];
    if (lane == 0) { s_sq[wid] = acc_sq; s_t3[wid] = acc_t3; }
    __syncthreads();

    __shared__ bool amLast;
    if (threadIdx.x == 0) {
        float r1 = 0.0f, r2 = 0.0f;
        #pragma unroll
        for (int w = 0; w < 8; w++) { r1 += s_sq[w]; r2 += s_t3[w]; }
        atomicAdd(&g_sum_sq, (double)r1);
        atomicAdd(&g_sum_t3, (double)r2);
        __threadfence();
        unsigned int ticket = atomicAdd(&g_count, 1u);
        amLast = (ticket == (unsigned int)gridDim.x - 1u);
    }
    __syncthreads();

    // finishing block computes the loss scalar. NO state mutation here —
    // all resets happen in pack_kernel of the next replay.
    if (amLast && threadIdx.x == 0) {
        double sumsq  = *((volatile double*)&g_sum_sq);
        double sum3   = *((volatile double*)&g_sum_t3);
        double sumlog = *((volatile double*)&g_sumlog);
        double Sd = (double)S;
        out[0] = (float)(ALPHA * sumsq - Sd * sumlog + sum3 / (Sd * Sd));
    }
}

// ---------------- launch ----------------
extern "C" void kernel_launch(void* const* d_in, const int* in_sizes, int n_in,
                              void* d_out, int out_size) {
    const float* inp = (const float*)d_in[0];
    const float* tgt = (const float*)d_in[1];
    float* out = (float*)d_out;

    long long n = in_sizes[0];
    int S = 1;
    while ((long long)(S + 1) * (S + 1) <= n) S++;   // integer sqrt (S = 4096)
    if (S > MAXS) S = MAXS;

    pack_kernel<<<(S * 32) / 256, 256>>>(inp, tgt, S);   // one warp per row
    main_kernel<<<GRID, 256>>>(inp, tgt, out, S);
}

// round 11
// speedup vs baseline: 1.0060x; 1.0060x over previous
#include <cuda_runtime.h>
#include <math.h>

// LineFinderLoss, S = 4096 (square). Output tuple packed: d_out[0] = loss,
// d_out[1 + i*S + j] = cost[i][j].
//
// cost[i][j] = 0.5*((in[i,0]-tg[j,0])^2 + (in[i,1]-tg[j,1])^2)
// loss = ALPHA*sum((in-tg)^2) - S*sum_n log(in[n,4]) + sum_ij (in[j,3]-tg[i,j])^2 / S^2

#define MAXS    4096
#define ALPHA   0.01
#define RTILE   4          // rows per ticket
#define OCC     5          // 5 blocks/SM, 48 regs, 40 warps/SM
#define GRID    (148 * OCC)   // 740 blocks -> 5920 warps, 185 per slice
#define NSLICE  32            // column slices of 128 cols (32 float4 per warp)
#define TSTRIDE 64            // uints between counters (256B: avoids LTS bit-7 pairing)

// ---------------- device scratch (no allocations allowed) ----------------
// Shifted packed columns: g_t0s[k] = target[k-1, 0]  (k = 1..S), g_t0s[0] junk.
__device__ float  g_t0s[MAXS + 4];
__device__ float  g_t1s[MAXS + 4];
__device__ float  g_ic3[MAXS + 4];       // input[:,3] (unshifted)
__device__ float  g_a0[MAXS];            // input[:,0]  (row scalars)
__device__ float  g_a1[MAXS];            // input[:,1]
__device__ double g_sumlog;              // sum_n log(input[n,4])
__device__ double g_sum_sq;
__device__ double g_sum_t3;
__device__ unsigned int g_tick[NSLICE * TSTRIDE];  // per-slice row-group counters
__device__ unsigned int g_count;         // completion counter

// ---------------- kernel 1: reset state + thread-per-row gather -------------
// Thread-per-row (16 blocks): each thread issues its row's 5 independent
// scattered loads (MLP=5, one latency round trip) + logf. Measurably faster
// than the warp-per-row variant (R8/R10 total-main gap grew ~3us with it).
// All replay-state resets live here, ordered before main_kernel by the
// kernel boundary.
__global__ void pack_kernel(const float* __restrict__ inp,
                            const float* __restrict__ tgt, int S) {
    if (blockIdx.x == 0) {
        if (threadIdx.x < NSLICE) g_tick[threadIdx.x * TSTRIDE] = 0u;
        if (threadIdx.x == 0) {
            g_count  = 0u;
            g_sum_sq = 0.0;
            g_sum_t3 = 0.0;
            g_sumlog = 0.0;
        }
    }
    int r = blockIdx.x * blockDim.x + threadIdx.x;
    float lg = 0.0f;
    if (r < S) {
        size_t base = (size_t)r * S;
        g_t0s[r + 1] = tgt[base + 0];
        g_t1s[r + 1] = tgt[base + 1];
        g_a0[r]      = inp[base + 0];
        g_a1[r]      = inp[base + 1];
        g_ic3[r]     = inp[base + 3];
        lg = logf(inp[base + 4]);
        if (r == 0) { g_t0s[0] = 0.0f; g_t1s[0] = 0.0f; }
    }
    #pragma unroll
    for (int off = 16; off > 0; off >>= 1)
        lg += __shfl_down_sync(0xffffffffu, lg, off);
    __shared__ float ws[8];
    int lane = threadIdx.x & 31, wid = threadIdx.x >> 5;
    if (lane == 0) ws[wid] = lg;
    __syncthreads();
    if (threadIdx.x == 0) {
        float s = 0.0f;
        #pragma unroll
        for (int w = 0; w < 8; w++) s += ws[w];
        atomicAdd(&g_sumlog, (double)s);
    }
}

// ---------------- per-row worker for main kernel ---------------------------
__device__ __forceinline__ void do_row(
    const float4 in, const float4 tg, int row, size_t base, int j4,
    bool isFirst, bool isLast,
    const float4 t0s, const float4 t1s, const float4 c3,
    float* __restrict__ out, int S,
    float& accq, float& acct)
{
    const float a0 = g_a0[row];   // broadcast, L1-resident
    const float a1 = g_a1[row];

    float d, e, u, v;
    d = in.x - tg.x; accq = fmaf(d, d, accq);
    e = c3.x - tg.x; acct = fmaf(e, e, acct);
    d = in.y - tg.y; accq = fmaf(d, d, accq);
    e = c3.y - tg.y; acct = fmaf(e, e, acct);
    d = in.z - tg.z; accq = fmaf(d, d, accq);
    e = c3.z - tg.z; acct = fmaf(e, e, acct);
    d = in.w - tg.w; accq = fmaf(d, d, accq);
    e = c3.w - tg.w; acct = fmaf(e, e, acct);

    float4 cv;
    u = a0 - t0s.x; v = a1 - t1s.x; cv.x = 0.5f * fmaf(u, u, v * v);
    u = a0 - t0s.y; v = a1 - t1s.y; cv.y = 0.5f * fmaf(u, u, v * v);
    u = a0 - t0s.z; v = a1 - t1s.z; cv.z = 0.5f * fmaf(u, u, v * v);
    u = a0 - t0s.w; v = a1 - t1s.w; cv.w = 0.5f * fmaf(u, u, v * v);

    if (!isFirst) {
        // out + base + 4*j4 == cost + base + (4*j4 - 1), 16B aligned
        ((float4*)(out + base))[j4] = cv;
    } else {
        float* crow = out + 1 + base;   // cost row start (cols 0..2)
        crow[0] = cv.y; crow[1] = cv.z; crow[2] = cv.w;
    }
    if (isLast) {
        u = a0 - g_t0s[S]; v = a1 - g_t1s[S];
        out[1 + base + (size_t)(S - 1)] = 0.5f * fmaf(u, u, v * v);
    }
}

// ---------------- kernel 2: per-warp slices + per-warp tickets --------------
// UNCHANGED from R10 (best main: 29.3us, 4.97 TB/s). Each WARP owns a fixed
// 128-column slice (t0s/t1s/c3 in registers, loaded once) and pops 4-row
// groups from its slice's counter. NO barriers in the loop: warps free-run.
// Body software-pipelined in two halves to fit the 48-reg budget. Next
// ticket popped at body start (lane 0), consumed by __shfl at body end.
// Hard-bounded loop: terminates even on corrupt counter state.
__global__ __launch_bounds__(256, OCC)
void main_kernel(const float* __restrict__ inp,
                 const float* __restrict__ tgt,
                 float* __restrict__ out, int S) {
    const int lane  = threadIdx.x & 31;
    const int wid   = threadIdx.x >> 5;
    const int gw    = blockIdx.x * 8 + wid;          // global warp id
    const int slice = gw & (NSLICE - 1);
    const int j4    = slice * 32 + lane;             // float4 column index
    const int lastj4 = (S >> 2) - 1;
    const int groups = S / RTILE;                    // 1024
    const bool isFirst = (j4 == 0);
    const bool isLast  = (j4 == lastj4);

    // column-resident data: loaded ONCE per warp, lives in registers
    const float4 t0s = ((const float4*)g_t0s)[j4];   // t0[4j-1..4j+2]
    const float4 t1s = ((const float4*)g_t1s)[j4];
    const float4 c3  = ((const float4*)g_ic3)[j4];   // in[4j..4j+3, 3]

    unsigned int* tick = &g_tick[slice * TSTRIDE];
    float acc_sq0 = 0.0f, acc_sq1 = 0.0f;
    float acc_t30 = 0.0f, acc_t31 = 0.0f;

    unsigned int t = 0;
    if (lane == 0) t = atomicAdd(tick, 1u);
    t = __shfl_sync(0xffffffffu, t, 0);

    for (int p = 0; p < groups + 2; p++) {
        if (t >= (unsigned int)groups) break;
        unsigned int tn = 0;
        if (lane == 0) tn = atomicAdd(tick, 1u);     // prefetch (consumed at end)

        const int r0 = (int)t * RTILE;
        const size_t b0 = (size_t)r0 * S;

        // ---- half 1: rows A,B ----
        {
            const float4 iA = __ldcs((const float4*)(inp + b0) + j4);
            const float4 gA = __ldcs((const float4*)(tgt + b0) + j4);
            const float4 iB = __ldcs((const float4*)(inp + b0 + S) + j4);
            const float4 gB = __ldcs((const float4*)(tgt + b0 + S) + j4);
            do_row(iA, gA, r0 + 0, b0,     j4, isFirst, isLast,
                   t0s, t1s, c3, out, S, acc_sq0, acc_t30);
            do_row(iB, gB, r0 + 1, b0 + S, j4, isFirst, isLast,
                   t0s, t1s, c3, out, S, acc_sq1, acc_t31);
        }
        // ---- half 2: rows C,D ----
        {
            const float4 iC = __ldcs((const float4*)(inp + b0 + 2 * (size_t)S) + j4);
            const float4 gC = __ldcs((const float4*)(tgt + b0 + 2 * (size_t)S) + j4);
            const float4 iD = __ldcs((const float4*)(inp + b0 + 3 * (size_t)S) + j4);
            const float4 gD = __ldcs((const float4*)(tgt + b0 + 3 * (size_t)S) + j4);
            do_row(iC, gC, r0 + 2, b0 + 2 * (size_t)S, j4, isFirst, isLast,
                   t0s, t1s, c3, out, S, acc_sq0, acc_t30);
            do_row(iD, gD, r0 + 3, b0 + 3 * (size_t)S, j4, isFirst, isLast,
                   t0s, t1s, c3, out, S, acc_sq1, acc_t31);
        }

        t = __shfl_sync(0xffffffffu, tn, 0);         // consume prefetched ticket
    }

    float acc_sq = acc_sq0 + acc_sq1;
    float acc_t3 = acc_t30 + acc_t31;

    // block reduce (warps re-converge here after independent loops)
    #pragma unroll
    for (int off = 16; off > 0; off >>= 1) {
        acc_sq += __shfl_down_sync(0xffffffffu, acc_sq, off);
        acc_t3 += __shfl_down_sync(0xffffffffu, acc_t3, off);
    }
    __shared__ float s_sq[8], s_t3[8];
    if (lane == 0) { s_sq[wid] = acc_sq; s_t3[wid] = acc_t3; }
    __syncthreads();

    __shared__ bool amLast;
    if (threadIdx.x == 0) {
        float r1 = 0.0f, r2 = 0.0f;
        #pragma unroll
        for (int w = 0; w < 8; w++) { r1 += s_sq[w]; r2 += s_t3[w]; }
        atomicAdd(&g_sum_sq, (double)r1);
        atomicAdd(&g_sum_t3, (double)r2);
        __threadfence();
        unsigned int ticket = atomicAdd(&g_count, 1u);
        amLast = (ticket == (unsigned int)gridDim.x - 1u);
    }
    __syncthreads();

    // finishing block computes the loss scalar. NO state mutation here —
    // all resets happen in pack_kernel of the next replay.
    if (amLast && threadIdx.x == 0) {
        double sumsq  = *((volatile double*)&g_sum_sq);
        double sum3   = *((volatile double*)&g_sum_t3);
        double sumlog = *((volatile double*)&g_sumlog);
        double Sd = (double)S;
        out[0] = (float)(ALPHA * sumsq - Sd * sumlog + sum3 / (Sd * Sd));
    }
}

// ---------------- launch ----------------
extern "C" void kernel_launch(void* const* d_in, const int* in_sizes, int n_in,
                              void* d_out, int out_size) {
    const float* inp = (const float*)d_in[0];
    const float* tgt = (const float*)d_in[1];
    float* out = (float*)d_out;

    long long n = in_sizes[0];
    int S = 1;
    while ((long long)(S + 1) * (S + 1) <= n) S++;   // integer sqrt (S = 4096)
    if (S > MAXS) S = MAXS;

    pack_kernel<<<(S + 255) / 256, 256>>>(inp, tgt, S);   // thread-per-row
    main_kernel<<<GRID, 256>>>(inp, tgt, out, S);
}